// round 5
// baseline (speedup 1.0000x reference)
#include <cuda_runtime.h>
#include <cuda_bf16.h>
#include <math.h>
#include <stdint.h>

// Problem shapes (fixed by the dataset)
#define Bb 4
#define Tt 16
#define Ss 256
#define Dd 512
#define Nn 8
#define Mm (Bb * Ss)   // 1024 GEMM rows
#define Kk Dd          // 512  GEMM K
#define Nc (Dd * Nn)   // 4096 GEMM cols

#define NCHUNKS 4
#define MCHUNK (Mm / NCHUNKS)       // 256 rows = 1 batch per chunk
#define ECHUNK (MCHUNK * Dd)        // 131072 encode cells per chunk

// ---------------------------------------------------------------------------
// Device scratch (no dynamic allocation allowed)
// ---------------------------------------------------------------------------
__device__ __align__(16) float         g_pop_rates[(size_t)Mm * Nc]; // 16.7 MB
__device__ __align__(16) __nv_bfloat16 g_Ehi[(size_t)Mm * Kk];       // [m][k]
__device__ __align__(16) __nv_bfloat16 g_Elo[(size_t)Mm * Kk];
__device__ __align__(16) __nv_bfloat16 g_Whi[(size_t)Kk * Nc];       // [k][n]
__device__ __align__(16) __nv_bfloat16 g_Wlo[(size_t)Kk * Nc];

// ---------------------------------------------------------------------------
// Fused bf16 hi/lo split conversion for E and W (elementwise, float4).
// ---------------------------------------------------------------------------
#define E_F4 ((Mm * Kk) / 4)      // 131072
#define W_F4 ((Kk * Nc) / 4)      // 524288

__device__ __forceinline__ void split4(float4 v, ushort4& hi, ushort4& lo) {
    __nv_bfloat16 h;
    h = __float2bfloat16(v.x); hi.x = __bfloat16_as_ushort(h);
    lo.x = __bfloat16_as_ushort(__float2bfloat16(v.x - __bfloat162float(h)));
    h = __float2bfloat16(v.y); hi.y = __bfloat16_as_ushort(h);
    lo.y = __bfloat16_as_ushort(__float2bfloat16(v.y - __bfloat162float(h)));
    h = __float2bfloat16(v.z); hi.z = __bfloat16_as_ushort(h);
    lo.z = __bfloat16_as_ushort(__float2bfloat16(v.z - __bfloat162float(h)));
    h = __float2bfloat16(v.w); hi.w = __bfloat16_as_ushort(h);
    lo.w = __bfloat16_as_ushort(__float2bfloat16(v.w - __bfloat162float(h)));
}

__global__ __launch_bounds__(256) void conv_kernel(const float* __restrict__ E,
                                                   const float* __restrict__ W) {
    int i = blockIdx.x * 256 + threadIdx.x;
    if (i < E_F4) {
        float4 v = ((const float4*)E)[i];
        ushort4 hi, lo;
        split4(v, hi, lo);
        ((ushort4*)g_Ehi)[i] = hi;
        ((ushort4*)g_Elo)[i] = lo;
    } else {
        int j = i - E_F4;
        if (j < W_F4) {
            float4 v = ((const float4*)W)[j];
            ushort4 hi, lo;
            split4(v, hi, lo);
            ((ushort4*)g_Whi)[j] = hi;
            ((ushort4*)g_Wlo)[j] = lo;
        }
    }
}

// ---------------------------------------------------------------------------
// mma.sync bf16 GEMM (3-term Markidis split) + bias + sigmoid epilogue.
// CTA tile 64x128, BK=32, 8 warps (warp tile 32x32), double-buffered cp.async.
// Chunked along M so chunks pipeline with the encode kernel.
// ---------------------------------------------------------------------------
#define BM 64
#define BN 128
#define BK 32
#define NK (Kk / BK)          // 16 stages

#define A_PITCH 40            // bf16 elems per A smem row (32 + 8 pad) -> 80 B
#define B_PITCH 136           // bf16 elems per B smem row (128 + 8 pad) -> 272 B
#define A_BYTES (BM * A_PITCH * 2)   // 5120
#define B_BYTES (BK * B_PITCH * 2)   // 8704
#define ST_AH 0
#define ST_AL A_BYTES
#define ST_BH (2 * A_BYTES)
#define ST_BL (2 * A_BYTES + B_BYTES)
#define STAGE_BYTES (2 * A_BYTES + 2 * B_BYTES)   // 27648
#define GEMM_SMEM (2 * STAGE_BYTES)               // 55296

__device__ __forceinline__ uint32_t smem_u32(const void* p) {
    uint32_t a;
    asm("{ .reg .u64 t; cvta.to.shared.u64 t, %1; cvt.u32.u64 %0, t; }"
        : "=r"(a) : "l"(p));
    return a;
}
__device__ __forceinline__ void cp16(uint32_t dst, const void* src) {
    asm volatile("cp.async.cg.shared.global [%0], [%1], 16;"
                 :: "r"(dst), "l"(src) : "memory");
}
__device__ __forceinline__ void ldsm_x4(uint32_t* r, uint32_t addr) {
    asm volatile("ldmatrix.sync.aligned.m8n8.x4.shared.b16 {%0,%1,%2,%3}, [%4];"
                 : "=r"(r[0]), "=r"(r[1]), "=r"(r[2]), "=r"(r[3]) : "r"(addr));
}
__device__ __forceinline__ void ldsm_x4t(uint32_t* r, uint32_t addr) {
    asm volatile("ldmatrix.sync.aligned.m8n8.x4.trans.shared.b16 {%0,%1,%2,%3}, [%4];"
                 : "=r"(r[0]), "=r"(r[1]), "=r"(r[2]), "=r"(r[3]) : "r"(addr));
}
__device__ __forceinline__ void mma16816(float* d, const uint32_t* a, const uint32_t* b) {
    asm volatile(
        "mma.sync.aligned.m16n8k16.row.col.f32.bf16.bf16.f32 "
        "{%0,%1,%2,%3}, {%4,%5,%6,%7}, {%8,%9}, {%0,%1,%2,%3};"
        : "+f"(d[0]), "+f"(d[1]), "+f"(d[2]), "+f"(d[3])
        : "r"(a[0]), "r"(a[1]), "r"(a[2]), "r"(a[3]), "r"(b[0]), "r"(b[1]));
}

__global__ __launch_bounds__(256, 2) void gemm_mma_kernel(
    const float* __restrict__ bias, int bm_base) {
    extern __shared__ char smem[];
    const uint32_t sbase = smem_u32(smem);
    const int tid = threadIdx.x;
    const int wid = tid >> 5;
    const int ln = tid & 31;
    const int warp_m = wid & 1;       // 2 warps along M (32 rows each)
    const int warp_n = wid >> 1;      // 4 warps along N (32 cols each)
    const int bm = bm_base + blockIdx.y * BM;
    const int bn = blockIdx.x * BN;

    // --- cp.async tile loader ---
    // A: 256 16B-chunks per array: thread -> row tid>>2, seg tid&3
    const int a_row = tid >> 2, a_seg = tid & 3;
    // B: 512 chunks per array: rows tid>>4 and +16, seg tid&15
    const int b_row0 = tid >> 4, b_seg = tid & 15;
    const int b_row1 = b_row0 + 16;

    auto load_stage = [&](int it, int p) {
        const int k0 = it * BK;
        const uint32_t st = sbase + p * STAGE_BYTES;
        // A hi/lo
        {
            const size_t g = (size_t)(bm + a_row) * Kk + k0 + a_seg * 8;
            const uint32_t s = st + ST_AH + a_row * (A_PITCH * 2) + a_seg * 16;
            cp16(s, g_Ehi + g);
            cp16(s + (ST_AL - ST_AH), g_Elo + g);
        }
        // B hi/lo
        {
            const size_t g0 = (size_t)(k0 + b_row0) * Nc + bn + b_seg * 8;
            const size_t g1 = (size_t)(k0 + b_row1) * Nc + bn + b_seg * 8;
            const uint32_t s0 = st + ST_BH + b_row0 * (B_PITCH * 2) + b_seg * 16;
            const uint32_t s1 = st + ST_BH + b_row1 * (B_PITCH * 2) + b_seg * 16;
            cp16(s0, g_Whi + g0);
            cp16(s1, g_Whi + g1);
            cp16(s0 + (ST_BL - ST_BH), g_Wlo + g0);
            cp16(s1 + (ST_BL - ST_BH), g_Wlo + g1);
        }
        asm volatile("cp.async.commit_group;" ::: "memory");
    };

    float acc[2][4][4];
#pragma unroll
    for (int i = 0; i < 2; i++)
#pragma unroll
        for (int n = 0; n < 4; n++)
#pragma unroll
            for (int c = 0; c < 4; c++) acc[i][n][c] = 0.0f;

    const int lm_row = ln & 15;             // 0..15
    const int lm_half = ln >> 4;            // 0..1

    load_stage(0, 0);

    for (int it = 0; it < NK; it++) {
        const int p = it & 1;
        if (it + 1 < NK) load_stage(it + 1, p ^ 1);
        if (it + 1 < NK) { asm volatile("cp.async.wait_group 1;" ::: "memory"); }
        else             { asm volatile("cp.async.wait_group 0;" ::: "memory"); }
        __syncthreads();

        const uint32_t st = sbase + p * STAGE_BYTES;
        const uint32_t a_hi = st + ST_AH, a_lo = st + ST_AL;
        const uint32_t b_hi = st + ST_BH, b_lo = st + ST_BL;

#pragma unroll
        for (int j = 0; j < 2; j++) {       // k16 sub-steps within BK=32
            uint32_t ah[2][4], al[2][4], bh[4][2], bl[4][2];
#pragma unroll
            for (int i = 0; i < 2; i++) {
                const uint32_t off =
                    (uint32_t)(warp_m * 32 + i * 16 + lm_row) * (A_PITCH * 2)
                    + (uint32_t)(j * 16 + lm_half * 8) * 2;
                ldsm_x4(ah[i], a_hi + off);
                ldsm_x4(al[i], a_lo + off);
            }
#pragma unroll
            for (int p4 = 0; p4 < 2; p4++) {
                const uint32_t off =
                    (uint32_t)(j * 16 + lm_row) * (B_PITCH * 2)
                    + (uint32_t)(warp_n * 32 + p4 * 16 + lm_half * 8) * 2;
                uint32_t r[4];
                ldsm_x4t(r, b_hi + off);
                bh[2 * p4][0] = r[0]; bh[2 * p4][1] = r[1];
                bh[2 * p4 + 1][0] = r[2]; bh[2 * p4 + 1][1] = r[3];
                ldsm_x4t(r, b_lo + off);
                bl[2 * p4][0] = r[0]; bl[2 * p4][1] = r[1];
                bl[2 * p4 + 1][0] = r[2]; bl[2 * p4 + 1][1] = r[3];
            }
#pragma unroll
            for (int i = 0; i < 2; i++)
#pragma unroll
                for (int n = 0; n < 4; n++) {
                    mma16816(acc[i][n], ah[i], bh[n]);
                    mma16816(acc[i][n], ah[i], bl[n]);
                    mma16816(acc[i][n], al[i], bh[n]);
                }
        }
        __syncthreads();
    }

    // Epilogue: bias + sigmoid -> g_pop_rates
    const int er = ln >> 2;        // 0..7
    const int ec = (ln & 3) * 2;   // 0,2,4,6
#pragma unroll
    for (int i = 0; i < 2; i++) {
        const int row0 = bm + warp_m * 32 + i * 16 + er;
#pragma unroll
        for (int n = 0; n < 4; n++) {
            const int col = bn + warp_n * 32 + n * 8 + ec;
            const float b0 = __ldg(bias + col);
            const float b1 = __ldg(bias + col + 1);
            float2 v0, v1;
            v0.x = 1.0f / (1.0f + expf(-(acc[i][n][0] + b0)));
            v0.y = 1.0f / (1.0f + expf(-(acc[i][n][1] + b1)));
            v1.x = 1.0f / (1.0f + expf(-(acc[i][n][2] + b0)));
            v1.y = 1.0f / (1.0f + expf(-(acc[i][n][3] + b1)));
            *(float2*)(g_pop_rates + (size_t)row0 * Nc + col) = v0;
            *(float2*)(g_pop_rates + (size_t)(row0 + 8) * Nc + col) = v1;
        }
    }
}

// ---------------------------------------------------------------------------
// Accurate fp32 sin (Cody-Waite + degree-9 minimax); fast-math immune.
// ---------------------------------------------------------------------------
__device__ __forceinline__ float my_sinf(float x) {
    const float INV_PI = 0.318309886183790672f;
    const float PI_HI = 3.14159274101257324f;
    const float PI_LO = -8.74227765734758577e-08f;
    float kf = rintf(x * INV_PI);
    float r = fmaf(-kf, PI_HI, x);
    r = fmaf(-kf, PI_LO, r);
    float s = r * r;
    float p = fmaf(s, 2.6083159809786593e-06f, -1.9810690719168633e-04f);
    p = fmaf(s, p, 8.3330785855650902e-03f);
    p = fmaf(s, p, -1.6666659712791443e-01f);
    float res = fmaf(r * s, p, r);
    int k = (int)kf;
    return (k & 1) ? -res : res;
}

// ---------------------------------------------------------------------------
// Fused encoder (per M-chunk): one thread per (b,s,d), loop over T=16.
// ---------------------------------------------------------------------------
__global__ __launch_bounds__(256) void encode_kernel(
    const float* __restrict__ emb,
    const float* __restrict__ noise,
    const float* __restrict__ freq_bands,
    const float* __restrict__ enc_w,
    const float* __restrict__ rate_rand,
    const float* __restrict__ pop_rand,
    float* __restrict__ out,
    int idx0)
{
    const int idx = idx0 + blockIdx.x * 256 + threadIdx.x;
    const int d = idx & (Dd - 1);
    const int s = (idx >> 9) & (Ss - 1);
    const int b = idx >> 17;

    float w0 = enc_w[0], w1 = enc_w[1], w2 = enc_w[2], w3 = enc_w[3];
    {
        float mx = fmaxf(fmaxf(w0, w1), fmaxf(w2, w3));
        float e0 = expf(w0 - mx), e1 = expf(w1 - mx);
        float e2 = expf(w2 - mx), e3 = expf(w3 - mx);
        float inv = 1.0f / (e0 + e1 + e2 + e3);
        w0 = e0 * inv; w1 = e1 * inv; w2 = e2 * inv; w3 = e3 * inv;
    }

    const float e = emb[idx];
    const float nz = noise[idx];
    const float sig = 1.0f / (1.0f + expf(-e));
    float rate = sig * 0.9f + 0.05f + nz * 0.1f;
    rate = fminf(fmaxf(rate, 0.0f), 1.0f);
    const int st = (int)(sig * 15.0f);
    const float phase = sig * 6.28318530717958647692f;
    const float freq = freq_bands[d];

    const float4* prp = (const float4*)(g_pop_rates + (size_t)idx * Nn);
    const float4 pr0 = prp[0];
    const float4 pr1 = prp[1];

    const float tstep = 6.28318530717958647692f / 15.0f;
    const size_t base = (((size_t)b * Tt) * Ss + s) * Dd + d;
#pragma unroll 4
    for (int t = 0; t < Tt; t++) {
        const size_t o = base + (size_t)t * (Ss * Dd);
        const float rr = __ldcs(rate_rand + o);
        const float4* pp = (const float4*)(pop_rand + o * Nn);
        const float4 q0 = __ldcs(pp);
        const float4 q1 = __ldcs(pp + 1);
        int cnt = (q0.x < pr0.x) + (q0.y < pr0.y) + (q0.z < pr0.z) + (q0.w < pr0.w)
                + (q1.x < pr1.x) + (q1.y < pr1.y) + (q1.z < pr1.z) + (q1.w < pr1.w);

        const float wave = my_sinf(fmaf(freq, (float)t * tstep, phase));

        float val = w0 * ((rr < rate) ? 1.0f : 0.0f)
                  + w1 * ((t == st) ? 1.0f : 0.0f)
                  + w2 * ((float)cnt * 0.125f)
                  + w3 * ((wave > 0.5f) ? 1.0f : 0.0f);
        out[o] = val;
    }
}

// ---------------------------------------------------------------------------
// Launch: fork-join pipeline. GEMM chunks on the capture-origin (null)
// stream; each chunk's completion event releases the matching encode chunk
// on a forked stream, overlapping GEMM compute with DRAM streaming.
// ---------------------------------------------------------------------------
extern "C" void kernel_launch(void* const* d_in, const int* in_sizes, int n_in,
                              void* d_out, int out_size) {
    const float* emb       = (const float*)d_in[0];
    const float* popW      = (const float*)d_in[1];
    const float* popb      = (const float*)d_in[2];
    const float* freq      = (const float*)d_in[3];
    const float* encw      = (const float*)d_in[4];
    const float* noise     = (const float*)d_in[5];
    const float* rate_rand = (const float*)d_in[6];
    const float* pop_rand  = (const float*)d_in[7];
    float* out = (float*)d_out;

    cudaFuncSetAttribute(gemm_mma_kernel,
                         cudaFuncAttributeMaxDynamicSharedMemorySize, GEMM_SMEM);

    cudaStream_t s2;
    cudaStreamCreateWithFlags(&s2, cudaStreamNonBlocking);

    conv_kernel<<<(E_F4 + W_F4) / 256, 256>>>(emb, popW);

    for (int c = 0; c < NCHUNKS; c++) {
        gemm_mma_kernel<<<dim3(Nc / BN, MCHUNK / BM), 256, GEMM_SMEM>>>(
            popb, c * MCHUNK);
        cudaEvent_t ev;
        cudaEventCreateWithFlags(&ev, cudaEventDisableTiming);
        cudaEventRecord(ev, 0);
        cudaStreamWaitEvent(s2, ev, 0);
        encode_kernel<<<ECHUNK / 256, 256, 0, s2>>>(
            emb, noise, freq, encw, rate_rand, pop_rand, out, c * ECHUNK);
        cudaEventDestroy(ev);
    }

    cudaEvent_t fin;
    cudaEventCreateWithFlags(&fin, cudaEventDisableTiming);
    cudaEventRecord(fin, s2);
    cudaStreamWaitEvent(0, fin, 0);
    cudaEventDestroy(fin);
}

// round 6
// speedup vs baseline: 1.3627x; 1.3627x over previous
#include <cuda_runtime.h>
#include <cuda_bf16.h>
#include <math.h>
#include <stdint.h>

// Problem shapes (fixed by the dataset)
#define Bb 4
#define Tt 16
#define Ss 256
#define Dd 512
#define Nn 8
#define Mm (Bb * Ss)   // 1024 GEMM rows
#define Kk Dd          // 512  GEMM K
#define Nc (Dd * Nn)   // 4096 GEMM cols

// ---------------------------------------------------------------------------
// Device scratch (no dynamic allocation allowed)
// ---------------------------------------------------------------------------
__device__ __align__(16) float         g_pop_rates[(size_t)Mm * Nc]; // 16.7 MB
__device__ __align__(16) __nv_bfloat16 g_Ehi[(size_t)Mm * Kk];       // [m][k]
__device__ __align__(16) __nv_bfloat16 g_Elo[(size_t)Mm * Kk];
__device__ __align__(16) __nv_bfloat16 g_Whi[(size_t)Kk * Nc];       // [k][n]
__device__ __align__(16) __nv_bfloat16 g_Wlo[(size_t)Kk * Nc];

// ---------------------------------------------------------------------------
// Fused bf16 hi/lo split conversion for E and W (elementwise, float4, x2 ILP).
// ---------------------------------------------------------------------------
#define E_F4 ((Mm * Kk) / 4)      // 131072
#define W_F4 ((Kk * Nc) / 4)      // 524288

__device__ __forceinline__ void split4(float4 v, ushort4& hi, ushort4& lo) {
    __nv_bfloat16 h;
    h = __float2bfloat16(v.x); hi.x = __bfloat16_as_ushort(h);
    lo.x = __bfloat16_as_ushort(__float2bfloat16(v.x - __bfloat162float(h)));
    h = __float2bfloat16(v.y); hi.y = __bfloat16_as_ushort(h);
    lo.y = __bfloat16_as_ushort(__float2bfloat16(v.y - __bfloat162float(h)));
    h = __float2bfloat16(v.z); hi.z = __bfloat16_as_ushort(h);
    lo.z = __bfloat16_as_ushort(__float2bfloat16(v.z - __bfloat162float(h)));
    h = __float2bfloat16(v.w); hi.w = __bfloat16_as_ushort(h);
    lo.w = __bfloat16_as_ushort(__float2bfloat16(v.w - __bfloat162float(h)));
}

__device__ __forceinline__ void conv_one(int i, const float* E, const float* W) {
    if (i < E_F4) {
        float4 v = __ldg((const float4*)E + i);
        ushort4 hi, lo;
        split4(v, hi, lo);
        ((ushort4*)g_Ehi)[i] = hi;
        ((ushort4*)g_Elo)[i] = lo;
    } else {
        int j = i - E_F4;
        float4 v = __ldg((const float4*)W + j);
        ushort4 hi, lo;
        split4(v, hi, lo);
        ((ushort4*)g_Whi)[j] = hi;
        ((ushort4*)g_Wlo)[j] = lo;
    }
}

__global__ __launch_bounds__(256) void conv_kernel(const float* __restrict__ E,
                                                   const float* __restrict__ W) {
    int i = blockIdx.x * 512 + threadIdx.x;
    conv_one(i, E, W);
    conv_one(i + 256, E, W);
}

// ---------------------------------------------------------------------------
// mma.sync bf16 GEMM (3-term Markidis split) + bias + sigmoid epilogue.
// CTA tile 128x128, BK=32, 8 warps (warp tile 32x64), 4-stage cp.async.
// ---------------------------------------------------------------------------
#define BM 128
#define BN 128
#define BK 32
#define NK (Kk / BK)          // 16 iterations
#define STAGES 4

#define A_PITCH 40            // bf16 elems per A smem row (32 + 8 pad) -> 80 B
#define B_PITCH 136           // bf16 elems per B smem row (128 + 8 pad) -> 272 B
#define A_BYTES (BM * A_PITCH * 2)   // 10240
#define B_BYTES (BK * B_PITCH * 2)   // 8704
#define ST_AH 0
#define ST_AL A_BYTES
#define ST_BH (2 * A_BYTES)
#define ST_BL (2 * A_BYTES + B_BYTES)
#define STAGE_BYTES (2 * A_BYTES + 2 * B_BYTES)   // 37888
#define GEMM_SMEM (STAGES * STAGE_BYTES)          // 151552

__device__ __forceinline__ uint32_t smem_u32(const void* p) {
    uint32_t a;
    asm("{ .reg .u64 t; cvta.to.shared.u64 t, %1; cvt.u32.u64 %0, t; }"
        : "=r"(a) : "l"(p));
    return a;
}
__device__ __forceinline__ void cp16(uint32_t dst, const void* src) {
    asm volatile("cp.async.cg.shared.global [%0], [%1], 16;"
                 :: "r"(dst), "l"(src) : "memory");
}
__device__ __forceinline__ void ldsm_x4(uint32_t* r, uint32_t addr) {
    asm volatile("ldmatrix.sync.aligned.m8n8.x4.shared.b16 {%0,%1,%2,%3}, [%4];"
                 : "=r"(r[0]), "=r"(r[1]), "=r"(r[2]), "=r"(r[3]) : "r"(addr));
}
__device__ __forceinline__ void ldsm_x4t(uint32_t* r, uint32_t addr) {
    asm volatile("ldmatrix.sync.aligned.m8n8.x4.trans.shared.b16 {%0,%1,%2,%3}, [%4];"
                 : "=r"(r[0]), "=r"(r[1]), "=r"(r[2]), "=r"(r[3]) : "r"(addr));
}
__device__ __forceinline__ void mma16816(float* d, const uint32_t* a, const uint32_t* b) {
    asm volatile(
        "mma.sync.aligned.m16n8k16.row.col.f32.bf16.bf16.f32 "
        "{%0,%1,%2,%3}, {%4,%5,%6,%7}, {%8,%9}, {%0,%1,%2,%3};"
        : "+f"(d[0]), "+f"(d[1]), "+f"(d[2]), "+f"(d[3])
        : "r"(a[0]), "r"(a[1]), "r"(a[2]), "r"(a[3]), "r"(b[0]), "r"(b[1]));
}

__global__ __launch_bounds__(256, 1) void gemm_mma_kernel(const float* __restrict__ bias) {
    extern __shared__ char smem[];
    const uint32_t sbase = smem_u32(smem);
    const int tid = threadIdx.x;
    const int wid = tid >> 5;
    const int ln = tid & 31;
    const int warp_m = wid & 3;       // 4 warps along M (32 rows each)
    const int warp_n = wid >> 2;      // 2 warps along N (64 cols each)
    const int bm = blockIdx.y * BM;
    const int bn = blockIdx.x * BN;

    // --- cp.async tile loader thread mapping ---
    const int a_row0 = tid >> 2, a_seg = tid & 3;   // A: 512 chunks/array
    const int a_row1 = a_row0 + 64;
    const int b_row0 = tid >> 4, b_seg = tid & 15;  // B: 512 chunks/array
    const int b_row1 = b_row0 + 16;

    auto load_stage = [&](int it) {
        const int k0 = it * BK;
        const uint32_t st = sbase + (it & (STAGES - 1)) * STAGE_BYTES;
        {
            const size_t g0 = (size_t)(bm + a_row0) * Kk + k0 + a_seg * 8;
            const size_t g1 = (size_t)(bm + a_row1) * Kk + k0 + a_seg * 8;
            const uint32_t s0 = st + ST_AH + a_row0 * (A_PITCH * 2) + a_seg * 16;
            const uint32_t s1 = st + ST_AH + a_row1 * (A_PITCH * 2) + a_seg * 16;
            cp16(s0, g_Ehi + g0);
            cp16(s1, g_Ehi + g1);
            cp16(s0 + (ST_AL - ST_AH), g_Elo + g0);
            cp16(s1 + (ST_AL - ST_AH), g_Elo + g1);
        }
        {
            const size_t g0 = (size_t)(k0 + b_row0) * Nc + bn + b_seg * 8;
            const size_t g1 = (size_t)(k0 + b_row1) * Nc + bn + b_seg * 8;
            const uint32_t s0 = st + ST_BH + b_row0 * (B_PITCH * 2) + b_seg * 16;
            const uint32_t s1 = st + ST_BH + b_row1 * (B_PITCH * 2) + b_seg * 16;
            cp16(s0, g_Whi + g0);
            cp16(s1, g_Whi + g1);
            cp16(s0 + (ST_BL - ST_BH), g_Wlo + g0);
            cp16(s1 + (ST_BL - ST_BH), g_Wlo + g1);
        }
        asm volatile("cp.async.commit_group;" ::: "memory");
    };

    float acc[2][8][4];
#pragma unroll
    for (int i = 0; i < 2; i++)
#pragma unroll
        for (int n = 0; n < 8; n++)
#pragma unroll
            for (int c = 0; c < 4; c++) acc[i][n][c] = 0.0f;

    const int lm_row = ln & 15;
    const int lm_half = ln >> 4;

    // Prologue: fill STAGES-1 buffers
    load_stage(0);
    load_stage(1);
    load_stage(2);

    for (int it = 0; it < NK; it++) {
        __syncthreads();                       // buffer (it+3)&3 now free
        if (it + 3 < NK) load_stage(it + 3);
        // wait until stage `it` has landed
        if (it < NK - 3)      { asm volatile("cp.async.wait_group 3;" ::: "memory"); }
        else if (it == NK - 3){ asm volatile("cp.async.wait_group 2;" ::: "memory"); }
        else if (it == NK - 2){ asm volatile("cp.async.wait_group 1;" ::: "memory"); }
        else                  { asm volatile("cp.async.wait_group 0;" ::: "memory"); }
        __syncthreads();

        const uint32_t st = sbase + (it & (STAGES - 1)) * STAGE_BYTES;
        const uint32_t a_hi = st + ST_AH, a_lo = st + ST_AL;
        const uint32_t b_hi = st + ST_BH, b_lo = st + ST_BL;

#pragma unroll
        for (int j = 0; j < 2; j++) {          // k16 sub-steps within BK=32
            uint32_t ah[2][4], al[2][4], bh[8][2], bl[8][2];
#pragma unroll
            for (int i = 0; i < 2; i++) {
                const uint32_t off =
                    (uint32_t)(warp_m * 32 + i * 16 + lm_row) * (A_PITCH * 2)
                    + (uint32_t)(j * 16 + lm_half * 8) * 2;
                ldsm_x4(ah[i], a_hi + off);
                ldsm_x4(al[i], a_lo + off);
            }
#pragma unroll
            for (int p4 = 0; p4 < 4; p4++) {
                const uint32_t off =
                    (uint32_t)(j * 16 + lm_row) * (B_PITCH * 2)
                    + (uint32_t)(warp_n * 64 + p4 * 16 + lm_half * 8) * 2;
                uint32_t r[4];
                ldsm_x4t(r, b_hi + off);
                bh[2 * p4][0] = r[0]; bh[2 * p4][1] = r[1];
                bh[2 * p4 + 1][0] = r[2]; bh[2 * p4 + 1][1] = r[3];
                ldsm_x4t(r, b_lo + off);
                bl[2 * p4][0] = r[0]; bl[2 * p4][1] = r[1];
                bl[2 * p4 + 1][0] = r[2]; bl[2 * p4 + 1][1] = r[3];
            }
#pragma unroll
            for (int i = 0; i < 2; i++)
#pragma unroll
                for (int n = 0; n < 8; n++) {
                    mma16816(acc[i][n], ah[i], bh[n]);
                    mma16816(acc[i][n], ah[i], bl[n]);
                    mma16816(acc[i][n], al[i], bh[n]);
                }
        }
    }

    // Epilogue: bias + sigmoid -> g_pop_rates
    const int er = ln >> 2;
    const int ec = (ln & 3) * 2;
#pragma unroll
    for (int i = 0; i < 2; i++) {
        const int row0 = bm + warp_m * 32 + i * 16 + er;
#pragma unroll
        for (int n = 0; n < 8; n++) {
            const int col = bn + warp_n * 64 + n * 8 + ec;
            const float b0 = __ldg(bias + col);
            const float b1 = __ldg(bias + col + 1);
            float2 v0, v1;
            v0.x = 1.0f / (1.0f + expf(-(acc[i][n][0] + b0)));
            v0.y = 1.0f / (1.0f + expf(-(acc[i][n][1] + b1)));
            v1.x = 1.0f / (1.0f + expf(-(acc[i][n][2] + b0)));
            v1.y = 1.0f / (1.0f + expf(-(acc[i][n][3] + b1)));
            *(float2*)(g_pop_rates + (size_t)row0 * Nc + col) = v0;
            *(float2*)(g_pop_rates + (size_t)(row0 + 8) * Nc + col) = v1;
        }
    }
}

// ---------------------------------------------------------------------------
// Accurate fp32 sin (Cody-Waite + degree-9 minimax); fast-math immune.
// ---------------------------------------------------------------------------
__device__ __forceinline__ float my_sinf(float x) {
    const float INV_PI = 0.318309886183790672f;
    const float PI_HI = 3.14159274101257324f;
    const float PI_LO = -8.74227765734758577e-08f;
    float kf = rintf(x * INV_PI);
    float r = fmaf(-kf, PI_HI, x);
    r = fmaf(-kf, PI_LO, r);
    float s = r * r;
    float p = fmaf(s, 2.6083159809786593e-06f, -1.9810690719168633e-04f);
    p = fmaf(s, p, 8.3330785855650902e-03f);
    p = fmaf(s, p, -1.6666659712791443e-01f);
    float res = fmaf(r * s, p, r);
    int k = (int)kf;
    return (k & 1) ? -res : res;
}

// ---------------------------------------------------------------------------
// Fused encoder: one thread per (b,s,d), loop over T=16. Streaming loads.
// ---------------------------------------------------------------------------
__global__ __launch_bounds__(256) void encode_kernel(
    const float* __restrict__ emb,
    const float* __restrict__ noise,
    const float* __restrict__ freq_bands,
    const float* __restrict__ enc_w,
    const float* __restrict__ rate_rand,
    const float* __restrict__ pop_rand,
    float* __restrict__ out)
{
    const int idx = blockIdx.x * 256 + threadIdx.x;
    const int d = idx & (Dd - 1);
    const int s = (idx >> 9) & (Ss - 1);
    const int b = idx >> 17;

    float w0 = enc_w[0], w1 = enc_w[1], w2 = enc_w[2], w3 = enc_w[3];
    {
        float mx = fmaxf(fmaxf(w0, w1), fmaxf(w2, w3));
        float e0 = expf(w0 - mx), e1 = expf(w1 - mx);
        float e2 = expf(w2 - mx), e3 = expf(w3 - mx);
        float inv = 1.0f / (e0 + e1 + e2 + e3);
        w0 = e0 * inv; w1 = e1 * inv; w2 = e2 * inv; w3 = e3 * inv;
    }

    const float e = emb[idx];
    const float nz = noise[idx];
    const float sig = 1.0f / (1.0f + expf(-e));
    float rate = sig * 0.9f + 0.05f + nz * 0.1f;
    rate = fminf(fmaxf(rate, 0.0f), 1.0f);
    const int st = (int)(sig * 15.0f);
    const float phase = sig * 6.28318530717958647692f;
    const float freq = freq_bands[d];

    const float4* prp = (const float4*)(g_pop_rates + (size_t)idx * Nn);
    const float4 pr0 = prp[0];
    const float4 pr1 = prp[1];

    const float tstep = 6.28318530717958647692f / 15.0f;
    const size_t base = (((size_t)b * Tt) * Ss + s) * Dd + d;
#pragma unroll 4
    for (int t = 0; t < Tt; t++) {
        const size_t o = base + (size_t)t * (Ss * Dd);
        const float rr = __ldcs(rate_rand + o);
        const float4* pp = (const float4*)(pop_rand + o * Nn);
        const float4 q0 = __ldcs(pp);
        const float4 q1 = __ldcs(pp + 1);
        int cnt = (q0.x < pr0.x) + (q0.y < pr0.y) + (q0.z < pr0.z) + (q0.w < pr0.w)
                + (q1.x < pr1.x) + (q1.y < pr1.y) + (q1.z < pr1.z) + (q1.w < pr1.w);

        const float wave = my_sinf(fmaf(freq, (float)t * tstep, phase));

        float val = w0 * ((rr < rate) ? 1.0f : 0.0f)
                  + w1 * ((t == st) ? 1.0f : 0.0f)
                  + w2 * ((float)cnt * 0.125f)
                  + w3 * ((wave > 0.5f) ? 1.0f : 0.0f);
        out[o] = val;
    }
}

// ---------------------------------------------------------------------------
// Launch (serial, single stream — multi-stream overlap regressed in R5)
// ---------------------------------------------------------------------------
extern "C" void kernel_launch(void* const* d_in, const int* in_sizes, int n_in,
                              void* d_out, int out_size) {
    const float* emb       = (const float*)d_in[0];
    const float* popW      = (const float*)d_in[1];
    const float* popb      = (const float*)d_in[2];
    const float* freq      = (const float*)d_in[3];
    const float* encw      = (const float*)d_in[4];
    const float* noise     = (const float*)d_in[5];
    const float* rate_rand = (const float*)d_in[6];
    const float* pop_rand  = (const float*)d_in[7];
    float* out = (float*)d_out;

    cudaFuncSetAttribute(gemm_mma_kernel,
                         cudaFuncAttributeMaxDynamicSharedMemorySize, GEMM_SMEM);

    conv_kernel<<<(E_F4 + W_F4) / 512, 256>>>(emb, popW);
    gemm_mma_kernel<<<dim3(Nc / BN, Mm / BM), 256, GEMM_SMEM>>>(popb);
    encode_kernel<<<(Mm * Dd) / 256, 256>>>(emb, noise, freq, encw,
                                            rate_rand, pop_rand, out);
}

// round 7
// speedup vs baseline: 1.4755x; 1.0828x over previous
#include <cuda_runtime.h>
#include <cuda_bf16.h>
#include <math.h>
#include <stdint.h>

// Problem shapes (fixed by the dataset)
#define Bb 4
#define Tt 16
#define Ss 256
#define Dd 512
#define Nn 8
#define Mm (Bb * Ss)   // 1024 GEMM rows
#define Kk Dd          // 512  GEMM K
#define Nc (Dd * Nn)   // 4096 GEMM cols

// ---------------------------------------------------------------------------
// Device scratch (no dynamic allocation allowed)
// ---------------------------------------------------------------------------
__device__ __align__(16) float         g_pop_rates[(size_t)Mm * Nc]; // 16.7 MB
__device__ __align__(16) __nv_bfloat16 g_Ehi[(size_t)Mm * Kk];       // [m][k]
__device__ __align__(16) __nv_bfloat16 g_Elo[(size_t)Mm * Kk];
__device__ __align__(16) __nv_bfloat16 g_Whi[(size_t)Kk * Nc];       // [k][n]
__device__ __align__(16) __nv_bfloat16 g_Wlo[(size_t)Kk * Nc];

// ---------------------------------------------------------------------------
// Fused bf16 hi/lo split conversion for E and W (elementwise, float4).
// ---------------------------------------------------------------------------
#define E_F4 ((Mm * Kk) / 4)      // 131072
#define W_F4 ((Kk * Nc) / 4)      // 524288

__device__ __forceinline__ void split4(float4 v, ushort4& hi, ushort4& lo) {
    __nv_bfloat16 h;
    h = __float2bfloat16(v.x); hi.x = __bfloat16_as_ushort(h);
    lo.x = __bfloat16_as_ushort(__float2bfloat16(v.x - __bfloat162float(h)));
    h = __float2bfloat16(v.y); hi.y = __bfloat16_as_ushort(h);
    lo.y = __bfloat16_as_ushort(__float2bfloat16(v.y - __bfloat162float(h)));
    h = __float2bfloat16(v.z); hi.z = __bfloat16_as_ushort(h);
    lo.z = __bfloat16_as_ushort(__float2bfloat16(v.z - __bfloat162float(h)));
    h = __float2bfloat16(v.w); hi.w = __bfloat16_as_ushort(h);
    lo.w = __bfloat16_as_ushort(__float2bfloat16(v.w - __bfloat162float(h)));
}

__global__ __launch_bounds__(256) void conv_kernel(const float* __restrict__ E,
                                                   const float* __restrict__ W) {
    int i = blockIdx.x * 256 + threadIdx.x;
    if (i < E_F4) {
        float4 v = ((const float4*)E)[i];
        ushort4 hi, lo;
        split4(v, hi, lo);
        ((ushort4*)g_Ehi)[i] = hi;
        ((ushort4*)g_Elo)[i] = lo;
    } else {
        int j = i - E_F4;
        if (j < W_F4) {
            float4 v = ((const float4*)W)[j];
            ushort4 hi, lo;
            split4(v, hi, lo);
            ((ushort4*)g_Whi)[j] = hi;
            ((ushort4*)g_Wlo)[j] = lo;
        }
    }
}

// ---------------------------------------------------------------------------
// mma.sync bf16 GEMM (3-term Markidis split) + bias + sigmoid epilogue.
// CTA tile 64x128, 128 threads (warp tile 32x64), BK=32, 2-stage cp.async.
// 4 CTAs/SM -> 4 independent sync domains hide barrier/pipeline stalls.
// ---------------------------------------------------------------------------
#define BM 64
#define BN 128
#define BK 32
#define NK (Kk / BK)          // 16 iterations

#define A_PITCH 40            // bf16 elems per A smem row (32 + 8 pad) -> 80 B
#define B_PITCH 136           // bf16 elems per B smem row (128 + 8 pad) -> 272 B
#define A_BYTES (BM * A_PITCH * 2)   // 5120
#define B_BYTES (BK * B_PITCH * 2)   // 8704
#define ST_AH 0
#define ST_AL A_BYTES
#define ST_BH (2 * A_BYTES)
#define ST_BL (2 * A_BYTES + B_BYTES)
#define STAGE_BYTES (2 * A_BYTES + 2 * B_BYTES)   // 27648
#define GEMM_SMEM (2 * STAGE_BYTES)               // 55296

__device__ __forceinline__ uint32_t smem_u32(const void* p) {
    uint32_t a;
    asm("{ .reg .u64 t; cvta.to.shared.u64 t, %1; cvt.u32.u64 %0, t; }"
        : "=r"(a) : "l"(p));
    return a;
}
__device__ __forceinline__ void cp16(uint32_t dst, const void* src) {
    asm volatile("cp.async.cg.shared.global [%0], [%1], 16;"
                 :: "r"(dst), "l"(src) : "memory");
}
__device__ __forceinline__ void ldsm_x4(uint32_t* r, uint32_t addr) {
    asm volatile("ldmatrix.sync.aligned.m8n8.x4.shared.b16 {%0,%1,%2,%3}, [%4];"
                 : "=r"(r[0]), "=r"(r[1]), "=r"(r[2]), "=r"(r[3]) : "r"(addr));
}
__device__ __forceinline__ void ldsm_x4t(uint32_t* r, uint32_t addr) {
    asm volatile("ldmatrix.sync.aligned.m8n8.x4.trans.shared.b16 {%0,%1,%2,%3}, [%4];"
                 : "=r"(r[0]), "=r"(r[1]), "=r"(r[2]), "=r"(r[3]) : "r"(addr));
}
__device__ __forceinline__ void mma16816(float* d, const uint32_t* a, const uint32_t* b) {
    asm volatile(
        "mma.sync.aligned.m16n8k16.row.col.f32.bf16.bf16.f32 "
        "{%0,%1,%2,%3}, {%4,%5,%6,%7}, {%8,%9}, {%0,%1,%2,%3};"
        : "+f"(d[0]), "+f"(d[1]), "+f"(d[2]), "+f"(d[3])
        : "r"(a[0]), "r"(a[1]), "r"(a[2]), "r"(a[3]), "r"(b[0]), "r"(b[1]));
}

__global__ __launch_bounds__(128, 4) void gemm_mma_kernel(const float* __restrict__ bias) {
    extern __shared__ char smem[];
    const uint32_t sbase = smem_u32(smem);
    const int tid = threadIdx.x;
    const int wid = tid >> 5;
    const int ln = tid & 31;
    const int warp_m = wid & 1;       // 2 warps along M (32 rows each)
    const int warp_n = wid >> 1;      // 2 warps along N (64 cols each)
    const int bm = blockIdx.y * BM;
    const int bn = blockIdx.x * BN;

    // --- cp.async tile loader thread mapping (128 threads) ---
    // A: 256 16B-chunks per array -> 2 per thread: rows tid>>2, +32
    const int a_row0 = tid >> 2, a_seg = tid & 3;
    const int a_row1 = a_row0 + 32;
    // B: 512 chunks per array -> 4 per thread: rows tid>>4, +8, +16, +24
    const int b_row0 = tid >> 4, b_seg = tid & 15;

    auto load_stage = [&](int it, int p) {
        const int k0 = it * BK;
        const uint32_t st = sbase + p * STAGE_BYTES;
        {
            const size_t g0 = (size_t)(bm + a_row0) * Kk + k0 + a_seg * 8;
            const size_t g1 = (size_t)(bm + a_row1) * Kk + k0 + a_seg * 8;
            const uint32_t s0 = st + ST_AH + a_row0 * (A_PITCH * 2) + a_seg * 16;
            const uint32_t s1 = st + ST_AH + a_row1 * (A_PITCH * 2) + a_seg * 16;
            cp16(s0, g_Ehi + g0);
            cp16(s1, g_Ehi + g1);
            cp16(s0 + (ST_AL - ST_AH), g_Elo + g0);
            cp16(s1 + (ST_AL - ST_AH), g_Elo + g1);
        }
#pragma unroll
        for (int r = 0; r < 4; r++) {
            const int brow = b_row0 + r * 8;
            const size_t g = (size_t)(k0 + brow) * Nc + bn + b_seg * 8;
            const uint32_t s = st + ST_BH + brow * (B_PITCH * 2) + b_seg * 16;
            cp16(s, g_Whi + g);
            cp16(s + (ST_BL - ST_BH), g_Wlo + g);
        }
        asm volatile("cp.async.commit_group;" ::: "memory");
    };

    float acc[2][8][4];
#pragma unroll
    for (int i = 0; i < 2; i++)
#pragma unroll
        for (int n = 0; n < 8; n++)
#pragma unroll
            for (int c = 0; c < 4; c++) acc[i][n][c] = 0.0f;

    const int lm_row = ln & 15;
    const int lm_half = ln >> 4;

    load_stage(0, 0);

    for (int it = 0; it < NK; it++) {
        const int p = it & 1;
        if (it + 1 < NK) load_stage(it + 1, p ^ 1);
        if (it + 1 < NK) { asm volatile("cp.async.wait_group 1;" ::: "memory"); }
        else             { asm volatile("cp.async.wait_group 0;" ::: "memory"); }
        __syncthreads();

        const uint32_t st = sbase + p * STAGE_BYTES;
        const uint32_t a_hi = st + ST_AH, a_lo = st + ST_AL;
        const uint32_t b_hi = st + ST_BH, b_lo = st + ST_BL;

#pragma unroll
        for (int j = 0; j < 2; j++) {          // k16 sub-steps within BK=32
            uint32_t ah[2][4], al[2][4], bh[8][2], bl[8][2];
#pragma unroll
            for (int i = 0; i < 2; i++) {
                const uint32_t off =
                    (uint32_t)(warp_m * 32 + i * 16 + lm_row) * (A_PITCH * 2)
                    + (uint32_t)(j * 16 + lm_half * 8) * 2;
                ldsm_x4(ah[i], a_hi + off);
                ldsm_x4(al[i], a_lo + off);
            }
#pragma unroll
            for (int p4 = 0; p4 < 4; p4++) {
                const uint32_t off =
                    (uint32_t)(j * 16 + lm_row) * (B_PITCH * 2)
                    + (uint32_t)(warp_n * 64 + p4 * 16 + lm_half * 8) * 2;
                uint32_t r[4];
                ldsm_x4t(r, b_hi + off);
                bh[2 * p4][0] = r[0]; bh[2 * p4][1] = r[1];
                bh[2 * p4 + 1][0] = r[2]; bh[2 * p4 + 1][1] = r[3];
                ldsm_x4t(r, b_lo + off);
                bl[2 * p4][0] = r[0]; bl[2 * p4][1] = r[1];
                bl[2 * p4 + 1][0] = r[2]; bl[2 * p4 + 1][1] = r[3];
            }
#pragma unroll
            for (int i = 0; i < 2; i++)
#pragma unroll
                for (int n = 0; n < 8; n++) {
                    mma16816(acc[i][n], ah[i], bh[n]);
                    mma16816(acc[i][n], ah[i], bl[n]);
                    mma16816(acc[i][n], al[i], bh[n]);
                }
        }
        __syncthreads();
    }

    // Epilogue: bias + sigmoid -> g_pop_rates
    const int er = ln >> 2;
    const int ec = (ln & 3) * 2;
#pragma unroll
    for (int i = 0; i < 2; i++) {
        const int row0 = bm + warp_m * 32 + i * 16 + er;
#pragma unroll
        for (int n = 0; n < 8; n++) {
            const int col = bn + warp_n * 64 + n * 8 + ec;
            const float b0 = __ldg(bias + col);
            const float b1 = __ldg(bias + col + 1);
            float2 v0, v1;
            v0.x = 1.0f / (1.0f + expf(-(acc[i][n][0] + b0)));
            v0.y = 1.0f / (1.0f + expf(-(acc[i][n][1] + b1)));
            v1.x = 1.0f / (1.0f + expf(-(acc[i][n][2] + b0)));
            v1.y = 1.0f / (1.0f + expf(-(acc[i][n][3] + b1)));
            *(float2*)(g_pop_rates + (size_t)row0 * Nc + col) = v0;
            *(float2*)(g_pop_rates + (size_t)(row0 + 8) * Nc + col) = v1;
        }
    }
}

// ---------------------------------------------------------------------------
// Accurate fp32 sin (Cody-Waite + degree-9 minimax); fast-math immune.
// ---------------------------------------------------------------------------
__device__ __forceinline__ float my_sinf(float x) {
    const float INV_PI = 0.318309886183790672f;
    const float PI_HI = 3.14159274101257324f;
    const float PI_LO = -8.74227765734758577e-08f;
    float kf = rintf(x * INV_PI);
    float r = fmaf(-kf, PI_HI, x);
    r = fmaf(-kf, PI_LO, r);
    float s = r * r;
    float p = fmaf(s, 2.6083159809786593e-06f, -1.9810690719168633e-04f);
    p = fmaf(s, p, 8.3330785855650902e-03f);
    p = fmaf(s, p, -1.6666659712791443e-01f);
    float res = fmaf(r * s, p, r);
    int k = (int)kf;
    return (k & 1) ? -res : res;
}

// ---------------------------------------------------------------------------
// Fused encoder: one thread per (b,s,d), loop over T=16. Streaming loads.
// ---------------------------------------------------------------------------
__global__ __launch_bounds__(256) void encode_kernel(
    const float* __restrict__ emb,
    const float* __restrict__ noise,
    const float* __restrict__ freq_bands,
    const float* __restrict__ enc_w,
    const float* __restrict__ rate_rand,
    const float* __restrict__ pop_rand,
    float* __restrict__ out)
{
    const int idx = blockIdx.x * 256 + threadIdx.x;
    const int d = idx & (Dd - 1);
    const int s = (idx >> 9) & (Ss - 1);
    const int b = idx >> 17;

    float w0 = enc_w[0], w1 = enc_w[1], w2 = enc_w[2], w3 = enc_w[3];
    {
        float mx = fmaxf(fmaxf(w0, w1), fmaxf(w2, w3));
        float e0 = expf(w0 - mx), e1 = expf(w1 - mx);
        float e2 = expf(w2 - mx), e3 = expf(w3 - mx);
        float inv = 1.0f / (e0 + e1 + e2 + e3);
        w0 = e0 * inv; w1 = e1 * inv; w2 = e2 * inv; w3 = e3 * inv;
    }

    const float e = emb[idx];
    const float nz = noise[idx];
    const float sig = 1.0f / (1.0f + expf(-e));
    float rate = sig * 0.9f + 0.05f + nz * 0.1f;
    rate = fminf(fmaxf(rate, 0.0f), 1.0f);
    const int st = (int)(sig * 15.0f);
    const float phase = sig * 6.28318530717958647692f;
    const float freq = freq_bands[d];

    const float4* prp = (const float4*)(g_pop_rates + (size_t)idx * Nn);
    const float4 pr0 = prp[0];
    const float4 pr1 = prp[1];

    const float tstep = 6.28318530717958647692f / 15.0f;
    const size_t base = (((size_t)b * Tt) * Ss + s) * Dd + d;
#pragma unroll 4
    for (int t = 0; t < Tt; t++) {
        const size_t o = base + (size_t)t * (Ss * Dd);
        const float rr = __ldcs(rate_rand + o);
        const float4* pp = (const float4*)(pop_rand + o * Nn);
        const float4 q0 = __ldcs(pp);
        const float4 q1 = __ldcs(pp + 1);
        int cnt = (q0.x < pr0.x) + (q0.y < pr0.y) + (q0.z < pr0.z) + (q0.w < pr0.w)
                + (q1.x < pr1.x) + (q1.y < pr1.y) + (q1.z < pr1.z) + (q1.w < pr1.w);

        const float wave = my_sinf(fmaf(freq, (float)t * tstep, phase));

        float val = w0 * ((rr < rate) ? 1.0f : 0.0f)
                  + w1 * ((t == st) ? 1.0f : 0.0f)
                  + w2 * ((float)cnt * 0.125f)
                  + w3 * ((wave > 0.5f) ? 1.0f : 0.0f);
        out[o] = val;
    }
}

// ---------------------------------------------------------------------------
// Launch (serial, single stream)
// ---------------------------------------------------------------------------
extern "C" void kernel_launch(void* const* d_in, const int* in_sizes, int n_in,
                              void* d_out, int out_size) {
    const float* emb       = (const float*)d_in[0];
    const float* popW      = (const float*)d_in[1];
    const float* popb      = (const float*)d_in[2];
    const float* freq      = (const float*)d_in[3];
    const float* encw      = (const float*)d_in[4];
    const float* noise     = (const float*)d_in[5];
    const float* rate_rand = (const float*)d_in[6];
    const float* pop_rand  = (const float*)d_in[7];
    float* out = (float*)d_out;

    cudaFuncSetAttribute(gemm_mma_kernel,
                         cudaFuncAttributeMaxDynamicSharedMemorySize, GEMM_SMEM);

    conv_kernel<<<(E_F4 + W_F4) / 256, 256>>>(emb, popW);
    gemm_mma_kernel<<<dim3(Nc / BN, Mm / BM), 128, GEMM_SMEM>>>(popb);
    encode_kernel<<<(Mm * Dd) / 256, 256>>>(emb, noise, freq, encw,
                                            rate_rand, pop_rand, out);
}

// round 8
// speedup vs baseline: 1.4963x; 1.0141x over previous
#include <cuda_runtime.h>
#include <cuda_bf16.h>
#include <math.h>
#include <stdint.h>

// Problem shapes (fixed by the dataset)
#define Bb 4
#define Tt 16
#define Ss 256
#define Dd 512
#define Nn 8
#define Mm (Bb * Ss)   // 1024 GEMM rows
#define Kk Dd          // 512  GEMM K
#define Nc (Dd * Nn)   // 4096 GEMM cols

// ---------------------------------------------------------------------------
// Device scratch (no dynamic allocation allowed)
// ---------------------------------------------------------------------------
__device__ __align__(16) float         g_pop_rates[(size_t)Mm * Nc]; // 16.7 MB
__device__ __align__(16) __nv_bfloat16 g_Ehi[(size_t)Mm * Kk];       // [m][k]
__device__ __align__(16) __nv_bfloat16 g_Elo[(size_t)Mm * Kk];
__device__ __align__(16) __nv_bfloat16 g_Whi[(size_t)Kk * Nc];       // [k][n]
__device__ __align__(16) __nv_bfloat16 g_Wlo[(size_t)Kk * Nc];
__device__ int g_flags[16];            // per-64-row-block completion counters

// ---------------------------------------------------------------------------
// Fused bf16 hi/lo split conversion for E and W; also resets g_flags.
// ---------------------------------------------------------------------------
#define E_F4 ((Mm * Kk) / 4)      // 131072
#define W_F4 ((Kk * Nc) / 4)      // 524288

__device__ __forceinline__ void split4(float4 v, ushort4& hi, ushort4& lo) {
    __nv_bfloat16 h;
    h = __float2bfloat16(v.x); hi.x = __bfloat16_as_ushort(h);
    lo.x = __bfloat16_as_ushort(__float2bfloat16(v.x - __bfloat162float(h)));
    h = __float2bfloat16(v.y); hi.y = __bfloat16_as_ushort(h);
    lo.y = __bfloat16_as_ushort(__float2bfloat16(v.y - __bfloat162float(h)));
    h = __float2bfloat16(v.z); hi.z = __bfloat16_as_ushort(h);
    lo.z = __bfloat16_as_ushort(__float2bfloat16(v.z - __bfloat162float(h)));
    h = __float2bfloat16(v.w); hi.w = __bfloat16_as_ushort(h);
    lo.w = __bfloat16_as_ushort(__float2bfloat16(v.w - __bfloat162float(h)));
}

__global__ __launch_bounds__(256) void conv_kernel(const float* __restrict__ E,
                                                   const float* __restrict__ W) {
    if (blockIdx.x == 0 && threadIdx.x < 16) g_flags[threadIdx.x] = 0;
    int i = blockIdx.x * 256 + threadIdx.x;
    if (i < E_F4) {
        float4 v = ((const float4*)E)[i];
        ushort4 hi, lo;
        split4(v, hi, lo);
        ((ushort4*)g_Ehi)[i] = hi;
        ((ushort4*)g_Elo)[i] = lo;
    } else {
        int j = i - E_F4;
        if (j < W_F4) {
            float4 v = ((const float4*)W)[j];
            ushort4 hi, lo;
            split4(v, hi, lo);
            ((ushort4*)g_Whi)[j] = hi;
            ((ushort4*)g_Wlo)[j] = lo;
        }
    }
}

// ---------------------------------------------------------------------------
// mma.sync bf16 GEMM (3-term Markidis split) + bias + sigmoid epilogue.
// Persistent: 256 CTAs x 2 tiles (tile 64x128, BK=32, 2-stage cp.async).
// After each tile: release flag for its 64-row block.
// ---------------------------------------------------------------------------
#define BM 64
#define BN 128
#define BK 32
#define NK (Kk / BK)          // 16 iterations

#define A_PITCH 40
#define B_PITCH 136
#define A_BYTES (BM * A_PITCH * 2)   // 5120
#define B_BYTES (BK * B_PITCH * 2)   // 8704
#define ST_AH 0
#define ST_AL A_BYTES
#define ST_BH (2 * A_BYTES)
#define ST_BL (2 * A_BYTES + B_BYTES)
#define STAGE_BYTES (2 * A_BYTES + 2 * B_BYTES)   // 27648
#define GEMM_SMEM (2 * STAGE_BYTES)               // 55296

__device__ __forceinline__ uint32_t smem_u32(const void* p) {
    uint32_t a;
    asm("{ .reg .u64 t; cvta.to.shared.u64 t, %1; cvt.u32.u64 %0, t; }"
        : "=r"(a) : "l"(p));
    return a;
}
__device__ __forceinline__ void cp16(uint32_t dst, const void* src) {
    asm volatile("cp.async.cg.shared.global [%0], [%1], 16;"
                 :: "r"(dst), "l"(src) : "memory");
}
__device__ __forceinline__ void ldsm_x4(uint32_t* r, uint32_t addr) {
    asm volatile("ldmatrix.sync.aligned.m8n8.x4.shared.b16 {%0,%1,%2,%3}, [%4];"
                 : "=r"(r[0]), "=r"(r[1]), "=r"(r[2]), "=r"(r[3]) : "r"(addr));
}
__device__ __forceinline__ void ldsm_x4t(uint32_t* r, uint32_t addr) {
    asm volatile("ldmatrix.sync.aligned.m8n8.x4.trans.shared.b16 {%0,%1,%2,%3}, [%4];"
                 : "=r"(r[0]), "=r"(r[1]), "=r"(r[2]), "=r"(r[3]) : "r"(addr));
}
__device__ __forceinline__ void mma16816(float* d, const uint32_t* a, const uint32_t* b) {
    asm volatile(
        "mma.sync.aligned.m16n8k16.row.col.f32.bf16.bf16.f32 "
        "{%0,%1,%2,%3}, {%4,%5,%6,%7}, {%8,%9}, {%0,%1,%2,%3};"
        : "+f"(d[0]), "+f"(d[1]), "+f"(d[2]), "+f"(d[3])
        : "r"(a[0]), "r"(a[1]), "r"(a[2]), "r"(a[3]), "r"(b[0]), "r"(b[1]));
}

__global__ __launch_bounds__(128, 4) void gemm_mma_kernel(const float* __restrict__ bias) {
    // Allow the dependent encode kernel to start launching now.
    asm volatile("griddepcontrol.launch_dependents;" ::: "memory");

    extern __shared__ char smem[];
    const uint32_t sbase = smem_u32(smem);
    const int tid = threadIdx.x;
    const int wid = tid >> 5;
    const int ln = tid & 31;
    const int warp_m = wid & 1;       // 2 warps along M (32 rows each)
    const int warp_n = wid >> 1;      // 2 warps along N (64 cols each)
    const int cb = blockIdx.x & 31;
    const int rbase = blockIdx.x >> 5;   // 0..7
    const int bn = cb * BN;

    const int a_row0 = tid >> 2, a_seg = tid & 3;
    const int a_row1 = a_row0 + 32;
    const int b_row0 = tid >> 4, b_seg = tid & 15;

    const int lm_row = ln & 15;
    const int lm_half = ln >> 4;
    const int er = ln >> 2;
    const int ec = (ln & 3) * 2;

    for (int s = 0; s < 2; s++) {
        const int rb = rbase + 8 * s;     // row-blocks 0..7 first, then 8..15
        const int bm = rb * BM;

        auto load_stage = [&](int it, int p) {
            const int k0 = it * BK;
            const uint32_t st = sbase + p * STAGE_BYTES;
            {
                const size_t g0 = (size_t)(bm + a_row0) * Kk + k0 + a_seg * 8;
                const size_t g1 = (size_t)(bm + a_row1) * Kk + k0 + a_seg * 8;
                const uint32_t s0 = st + ST_AH + a_row0 * (A_PITCH * 2) + a_seg * 16;
                const uint32_t s1 = st + ST_AH + a_row1 * (A_PITCH * 2) + a_seg * 16;
                cp16(s0, g_Ehi + g0);
                cp16(s1, g_Ehi + g1);
                cp16(s0 + (ST_AL - ST_AH), g_Elo + g0);
                cp16(s1 + (ST_AL - ST_AH), g_Elo + g1);
            }
#pragma unroll
            for (int r = 0; r < 4; r++) {
                const int brow = b_row0 + r * 8;
                const size_t g = (size_t)(k0 + brow) * Nc + bn + b_seg * 8;
                const uint32_t sm = st + ST_BH + brow * (B_PITCH * 2) + b_seg * 16;
                cp16(sm, g_Whi + g);
                cp16(sm + (ST_BL - ST_BH), g_Wlo + g);
            }
            asm volatile("cp.async.commit_group;" ::: "memory");
        };

        float acc[2][8][4];
#pragma unroll
        for (int i = 0; i < 2; i++)
#pragma unroll
            for (int n = 0; n < 8; n++)
#pragma unroll
                for (int c = 0; c < 4; c++) acc[i][n][c] = 0.0f;

        load_stage(0, 0);

        for (int it = 0; it < NK; it++) {
            const int p = it & 1;
            if (it + 1 < NK) load_stage(it + 1, p ^ 1);
            if (it + 1 < NK) { asm volatile("cp.async.wait_group 1;" ::: "memory"); }
            else             { asm volatile("cp.async.wait_group 0;" ::: "memory"); }
            __syncthreads();

            const uint32_t st = sbase + p * STAGE_BYTES;
            const uint32_t a_hi = st + ST_AH, a_lo = st + ST_AL;
            const uint32_t b_hi = st + ST_BH, b_lo = st + ST_BL;

#pragma unroll
            for (int j = 0; j < 2; j++) {
                uint32_t ah[2][4], al[2][4], bh[8][2], bl[8][2];
#pragma unroll
                for (int i = 0; i < 2; i++) {
                    const uint32_t off =
                        (uint32_t)(warp_m * 32 + i * 16 + lm_row) * (A_PITCH * 2)
                        + (uint32_t)(j * 16 + lm_half * 8) * 2;
                    ldsm_x4(ah[i], a_hi + off);
                    ldsm_x4(al[i], a_lo + off);
                }
#pragma unroll
                for (int p4 = 0; p4 < 4; p4++) {
                    const uint32_t off =
                        (uint32_t)(j * 16 + lm_row) * (B_PITCH * 2)
                        + (uint32_t)(warp_n * 64 + p4 * 16 + lm_half * 8) * 2;
                    uint32_t r[4];
                    ldsm_x4t(r, b_hi + off);
                    bh[2 * p4][0] = r[0]; bh[2 * p4][1] = r[1];
                    bh[2 * p4 + 1][0] = r[2]; bh[2 * p4 + 1][1] = r[3];
                    ldsm_x4t(r, b_lo + off);
                    bl[2 * p4][0] = r[0]; bl[2 * p4][1] = r[1];
                    bl[2 * p4 + 1][0] = r[2]; bl[2 * p4 + 1][1] = r[3];
                }
#pragma unroll
                for (int i = 0; i < 2; i++)
#pragma unroll
                    for (int n = 0; n < 8; n++) {
                        mma16816(acc[i][n], ah[i], bh[n]);
                        mma16816(acc[i][n], ah[i], bl[n]);
                        mma16816(acc[i][n], al[i], bh[n]);
                    }
            }
            __syncthreads();
        }

        // Epilogue: bias + sigmoid -> g_pop_rates
#pragma unroll
        for (int i = 0; i < 2; i++) {
            const int row0 = bm + warp_m * 32 + i * 16 + er;
#pragma unroll
            for (int n = 0; n < 8; n++) {
                const int col = bn + warp_n * 64 + n * 8 + ec;
                const float b0 = __ldg(bias + col);
                const float b1 = __ldg(bias + col + 1);
                float2 v0, v1;
                v0.x = 1.0f / (1.0f + expf(-(acc[i][n][0] + b0)));
                v0.y = 1.0f / (1.0f + expf(-(acc[i][n][1] + b1)));
                v1.x = 1.0f / (1.0f + expf(-(acc[i][n][2] + b0)));
                v1.y = 1.0f / (1.0f + expf(-(acc[i][n][3] + b1)));
                *(float2*)(g_pop_rates + (size_t)row0 * Nc + col) = v0;
                *(float2*)(g_pop_rates + (size_t)(row0 + 8) * Nc + col) = v1;
            }
        }

        // Release this row-block (release pattern: fence by all, then atomic).
        __threadfence();
        __syncthreads();
        if (tid == 0) atomicAdd(&g_flags[rb], 1);
    }
}

// ---------------------------------------------------------------------------
// Accurate fp32 sin (Cody-Waite + degree-9 minimax); fast-math immune.
// ---------------------------------------------------------------------------
__device__ __forceinline__ float my_sinf(float x) {
    const float INV_PI = 0.318309886183790672f;
    const float PI_HI = 3.14159274101257324f;
    const float PI_LO = -8.74227765734758577e-08f;
    float kf = rintf(x * INV_PI);
    float r = fmaf(-kf, PI_HI, x);
    r = fmaf(-kf, PI_LO, r);
    float s = r * r;
    float p = fmaf(s, 2.6083159809786593e-06f, -1.9810690719168633e-04f);
    p = fmaf(s, p, 8.3330785855650902e-03f);
    p = fmaf(s, p, -1.6666659712791443e-01f);
    float res = fmaf(r * s, p, r);
    int k = (int)kf;
    return (k & 1) ? -res : res;
}

// ---------------------------------------------------------------------------
// Fused encoder: spins on its row-block flag, then streams. PDL secondary.
// ---------------------------------------------------------------------------
__global__ __launch_bounds__(256) void encode_kernel(
    const float* __restrict__ emb,
    const float* __restrict__ noise,
    const float* __restrict__ freq_bands,
    const float* __restrict__ enc_w,
    const float* __restrict__ rate_rand,
    const float* __restrict__ pop_rand,
    float* __restrict__ out)
{
    // Wait until this CTA's 64-row block of g_pop_rates is published.
    if (threadIdx.x == 0) {
        const int rb = blockIdx.x >> 7;   // (blockIdx*256)>>9 rows, >>6 blocks
        int v;
        for (;;) {
            asm volatile("ld.acquire.gpu.global.s32 %0, [%1];"
                         : "=r"(v) : "l"(&g_flags[rb]) : "memory");
            if (v >= 32) break;
            __nanosleep(128);
        }
    }
    __syncthreads();

    const int idx = blockIdx.x * 256 + threadIdx.x;
    const int d = idx & (Dd - 1);
    const int s = (idx >> 9) & (Ss - 1);
    const int b = idx >> 17;

    float w0 = enc_w[0], w1 = enc_w[1], w2 = enc_w[2], w3 = enc_w[3];
    {
        float mx = fmaxf(fmaxf(w0, w1), fmaxf(w2, w3));
        float e0 = expf(w0 - mx), e1 = expf(w1 - mx);
        float e2 = expf(w2 - mx), e3 = expf(w3 - mx);
        float inv = 1.0f / (e0 + e1 + e2 + e3);
        w0 = e0 * inv; w1 = e1 * inv; w2 = e2 * inv; w3 = e3 * inv;
    }

    const float e = emb[idx];
    const float nz = noise[idx];
    const float sig = 1.0f / (1.0f + expf(-e));
    float rate = sig * 0.9f + 0.05f + nz * 0.1f;
    rate = fminf(fmaxf(rate, 0.0f), 1.0f);
    const int st = (int)(sig * 15.0f);
    const float phase = sig * 6.28318530717958647692f;
    const float freq = freq_bands[d];

    const float4* prp = (const float4*)(g_pop_rates + (size_t)idx * Nn);
    const float4 pr0 = prp[0];
    const float4 pr1 = prp[1];

    const float tstep = 6.28318530717958647692f / 15.0f;
    const size_t base = (((size_t)b * Tt) * Ss + s) * Dd + d;
#pragma unroll 4
    for (int t = 0; t < Tt; t++) {
        const size_t o = base + (size_t)t * (Ss * Dd);
        const float rr = __ldcs(rate_rand + o);
        const float4* pp = (const float4*)(pop_rand + o * Nn);
        const float4 q0 = __ldcs(pp);
        const float4 q1 = __ldcs(pp + 1);
        int cnt = (q0.x < pr0.x) + (q0.y < pr0.y) + (q0.z < pr0.z) + (q0.w < pr0.w)
                + (q1.x < pr1.x) + (q1.y < pr1.y) + (q1.z < pr1.z) + (q1.w < pr1.w);

        const float wave = my_sinf(fmaf(freq, (float)t * tstep, phase));

        float val = w0 * ((rr < rate) ? 1.0f : 0.0f)
                  + w1 * ((t == st) ? 1.0f : 0.0f)
                  + w2 * ((float)cnt * 0.125f)
                  + w3 * ((wave > 0.5f) ? 1.0f : 0.0f);
        __stcs(out + o, val);
    }
}

// ---------------------------------------------------------------------------
// Launch: conv -> GEMM (primary) -> encode (PDL secondary, flag-gated).
// ---------------------------------------------------------------------------
extern "C" void kernel_launch(void* const* d_in, const int* in_sizes, int n_in,
                              void* d_out, int out_size) {
    const float* emb       = (const float*)d_in[0];
    const float* popW      = (const float*)d_in[1];
    const float* popb      = (const float*)d_in[2];
    const float* freq      = (const float*)d_in[3];
    const float* encw      = (const float*)d_in[4];
    const float* noise     = (const float*)d_in[5];
    const float* rate_rand = (const float*)d_in[6];
    const float* pop_rand  = (const float*)d_in[7];
    float* out = (float*)d_out;

    cudaFuncSetAttribute(gemm_mma_kernel,
                         cudaFuncAttributeMaxDynamicSharedMemorySize, GEMM_SMEM);

    conv_kernel<<<(E_F4 + W_F4) / 256, 256>>>(emb, popW);
    gemm_mma_kernel<<<256, 128, GEMM_SMEM>>>(popb);

    cudaLaunchConfig_t cfg = {};
    cfg.gridDim = dim3((Mm * Dd) / 256);
    cfg.blockDim = dim3(256);
    cfg.dynamicSmemBytes = 0;
    cfg.stream = 0;
    cudaLaunchAttribute attrs[1];
    attrs[0].id = cudaLaunchAttributeProgrammaticStreamSerialization;
    attrs[0].val.programmaticStreamSerializationAllowed = 1;
    cfg.attrs = attrs;
    cfg.numAttrs = 1;
    cudaLaunchKernelEx(&cfg, encode_kernel,
                       emb, noise, freq, encw, rate_rand, pop_rand, out);
}